// round 7
// baseline (speedup 1.0000x reference)
#include <cuda_runtime.h>
#include <cuda_bf16.h>
#include <cstdint>

#define NB 8
#define NC 256
#define NHW 4096
#define ND 32

typedef unsigned long long ull;

// Static device scratch
__device__ __nv_bfloat16 g_Qb[NB][NHW][ND];    // q * log2(e), [b][n][d] bf16
__device__ __nv_bfloat16 g_Kb[NB][NHW][ND];    // [b][n][d] bf16
__device__ __nv_bfloat16 g_Vb[NB][NC][NHW];    // [b][e][n] bf16

// ---------------------------------------------------------------------------
// helpers
// ---------------------------------------------------------------------------
__device__ __forceinline__ uint32_t smem_u32(const void* p) {
    uint32_t a;
    asm("{ .reg .u64 t; cvta.to.shared.u64 t, %1; cvt.u32.u64 %0, t; }"
        : "=r"(a) : "l"(p));
    return a;
}
__device__ __forceinline__ float fexp2(float v) {
    float r; asm("ex2.approx.ftz.f32 %0, %1;" : "=f"(r) : "f"(v)); return r;
}
// d = {hi, lo} packed bf16x2
__device__ __forceinline__ uint32_t pack_bf16(float hi, float lo) {
    uint32_t r; asm("cvt.rn.bf16x2.f32 %0, %1, %2;" : "=r"(r) : "f"(hi), "f"(lo));
    return r;
}
__device__ __forceinline__ void mma_bf16(float c[4], const uint32_t a[4],
                                         uint32_t b0, uint32_t b1) {
    asm volatile(
        "mma.sync.aligned.m16n8k16.row.col.f32.bf16.bf16.f32 "
        "{%0,%1,%2,%3}, {%4,%5,%6,%7}, {%8,%9}, {%0,%1,%2,%3};"
        : "+f"(c[0]), "+f"(c[1]), "+f"(c[2]), "+f"(c[3])
        : "r"(a[0]), "r"(a[1]), "r"(a[2]), "r"(a[3]), "r"(b0), "r"(b1));
}
__device__ __forceinline__ void ldmx4(uint32_t r[4], uint32_t a) {
    asm volatile("ldmatrix.sync.aligned.m8n8.x4.shared.b16 {%0,%1,%2,%3}, [%4];"
        : "=r"(r[0]), "=r"(r[1]), "=r"(r[2]), "=r"(r[3]) : "r"(a));
}
__device__ __forceinline__ void ldmx4t(uint32_t r[4], uint32_t a) {
    asm volatile("ldmatrix.sync.aligned.m8n8.x4.trans.shared.b16 {%0,%1,%2,%3}, [%4];"
        : "=r"(r[0]), "=r"(r[1]), "=r"(r[2]), "=r"(r[3]) : "r"(a));
}
__device__ __forceinline__ void cpa16(uint32_t s, const void* g) {
    asm volatile("cp.async.cg.shared.global [%0], [%1], 16;"
                 :: "r"(s), "l"(__cvta_generic_to_global(g)) : "memory");
}
#define CP_COMMIT() asm volatile("cp.async.commit_group;" ::: "memory")
#define CP_WAIT1()  asm volatile("cp.async.wait_group 1;" ::: "memory")
#define CP_WAIT0()  asm volatile("cp.async.wait_group 0;" ::: "memory")

// ============================================================================
// Kernel A: fused QKV projection, bf16 tensor cores.
// Out[320][4096] per batch; CTA = 64 oc x 256 n; 8 warps = 2 ocg x 4 ng.
//   oc0==0 CTA: rows 0-31 -> Q (x log2e), rows 32-63 -> K, stored [n][d] bf16
//   else:       rows -> V [e][n] bf16
// ============================================================================
#define QW_PITCH 528           // bytes per 256-col bf16 row (+16B pad)
#define OFF_W 0                // bf16 [64] rows
#define OFF_BIAS 33792         // 64 f32
#define OFF_X 34048            // bf16 [32] rows, pitch 528
#define QKV_SMEM2 50944

__global__ __launch_bounds__(256) void qkv_kernel(
    const float* __restrict__ x,
    const float* __restrict__ Wq, const float* __restrict__ bq,
    const float* __restrict__ Wk, const float* __restrict__ bk,
    const float* __restrict__ Wv, const float* __restrict__ bv)
{
    extern __shared__ char sm[];
    const uint32_t sb = smem_u32(sm);
    const int b = blockIdx.z;
    const int oc0 = blockIdx.y * 64;
    const int n0 = blockIdx.x * 256;
    const int t = threadIdx.x, wid = t >> 5, lane = t & 31;
    const int wOC = wid & 1, wN = wid >> 1;
    const int r = lane >> 2, tq = lane & 3;

    // ---- W -> bf16 smem ----
    #pragma unroll
    for (int l = 0; l < 16; l++) {
        int idx = t + l * 256;                 // 64 rows x 64 float4
        int row = idx >> 6, c4 = idx & 63;
        const float* src;
        if (oc0 == 0) src = (row < 32) ? &Wq[row * 256 + c4 * 4]
                                       : &Wk[(row - 32) * 256 + c4 * 4];
        else          src = &Wv[(oc0 - 64 + row) * 256 + c4 * 4];
        float4 w = *(const float4*)src;
        *(uint2*)(sm + OFF_W + row * QW_PITCH + c4 * 8) =
            make_uint2(pack_bf16(w.y, w.x), pack_bf16(w.w, w.z));
    }
    if (t < 64) {
        float bias;
        if (oc0 == 0) bias = (t < 32) ? bq[t] : bk[t - 32];
        else          bias = bv[oc0 - 64 + t];
        ((float*)(sm + OFF_BIAS))[t] = bias;
    }

    float acc[2][8][4];
    #pragma unroll
    for (int m = 0; m < 2; m++)
        #pragma unroll
        for (int j = 0; j < 8; j++)
            #pragma unroll
            for (int q = 0; q < 4; q++) acc[m][j][q] = 0.f;

    // prefetch x chunk 0 into regs
    float4 xr[8];
    #pragma unroll
    for (int l = 0; l < 8; l++) {
        int idx = t + l * 256;
        int cc = idx >> 6, n4 = idx & 63;
        xr[l] = *(const float4*)&x[(b * NC + cc) * NHW + n0 + n4 * 4];
    }

    for (int ch = 0; ch < 8; ch++) {
        __syncthreads();                       // X stage free (W visible after 1st)
        #pragma unroll
        for (int l = 0; l < 8; l++) {
            int idx = t + l * 256;
            int cc = idx >> 6, n4 = idx & 63;
            *(uint2*)(sm + OFF_X + cc * QW_PITCH + n4 * 8) =
                make_uint2(pack_bf16(xr[l].y, xr[l].x), pack_bf16(xr[l].w, xr[l].z));
        }
        __syncthreads();
        if (ch + 1 < 8) {
            int c0n = (ch + 1) * 32;
            #pragma unroll
            for (int l = 0; l < 8; l++) {
                int idx = t + l * 256;
                int cc = idx >> 6, n4 = idx & 63;
                xr[l] = *(const float4*)&x[(b * NC + c0n + cc) * NHW + n0 + n4 * 4];
            }
        }
        #pragma unroll
        for (int ks = 0; ks < 2; ks++) {
            const int cb = ks * 16;
            uint32_t a0[4], a1[4];
            uint32_t wadr = sb + OFF_W + (wOC * 32 + (lane & 15)) * QW_PITCH
                            + (ch * 32 + cb) * 2 + (lane >> 4) * 16;
            ldmx4(a0, wadr);
            ldmx4(a1, wadr + 16 * QW_PITCH);
            uint32_t bt[4][4];
            #pragma unroll
            for (int nb = 0; nb < 4; nb++) {
                uint32_t xadr = sb + OFF_X
                    + (cb + (lane & 7) + ((lane >> 3) & 1) * 8) * QW_PITCH
                    + (wN * 64 + nb * 16 + (lane >> 4) * 8) * 2;
                ldmx4t(bt[nb], xadr);
            }
            #pragma unroll
            for (int nb = 0; nb < 4; nb++) {
                mma_bf16(acc[0][nb * 2],     a0, bt[nb][0], bt[nb][1]);
                mma_bf16(acc[0][nb * 2 + 1], a0, bt[nb][2], bt[nb][3]);
                mma_bf16(acc[1][nb * 2],     a1, bt[nb][0], bt[nb][1]);
                mma_bf16(acc[1][nb * 2 + 1], a1, bt[nb][2], bt[nb][3]);
            }
        }
    }
    __syncthreads();

    // bias into regs before smem reuse
    const float* bs = (const float*)(sm + OFF_BIAS);
    float bm[2][2];
    bm[0][0] = bs[wOC * 32 + r];      bm[0][1] = bs[wOC * 32 + r + 8];
    bm[1][0] = bs[wOC * 32 + 16 + r]; bm[1][1] = bs[wOC * 32 + 16 + r + 8];
    __syncthreads();

    if (oc0 == 0) {
        // transpose-stage: Ot bf16 [256 n][72] pitch 144B
        const float scl = (wOC == 0) ? 1.4426950408889634f : 1.0f;
        #pragma unroll
        for (int m = 0; m < 2; m++) {
            int oc_r0 = wOC * 32 + m * 16 + r;
            #pragma unroll
            for (int j = 0; j < 8; j++) {
                int n_ = wN * 64 + j * 8 + tq * 2;
                *(__nv_bfloat16*)(sm + n_ * 144 + oc_r0 * 2) =
                    __float2bfloat16((acc[m][j][0] + bm[m][0]) * scl);
                *(__nv_bfloat16*)(sm + (n_ + 1) * 144 + oc_r0 * 2) =
                    __float2bfloat16((acc[m][j][1] + bm[m][0]) * scl);
                *(__nv_bfloat16*)(sm + n_ * 144 + (oc_r0 + 8) * 2) =
                    __float2bfloat16((acc[m][j][2] + bm[m][1]) * scl);
                *(__nv_bfloat16*)(sm + (n_ + 1) * 144 + (oc_r0 + 8) * 2) =
                    __float2bfloat16((acc[m][j][3] + bm[m][1]) * scl);
            }
        }
        __syncthreads();
        #pragma unroll
        for (int l = 0; l < 4; l++) {
            int idx = t + l * 256;
            int nn = idx >> 2, c4 = idx & 3;
            *(float4*)&g_Qb[b][n0 + nn][c4 * 8] =
                *(const float4*)(sm + nn * 144 + c4 * 16);
            *(float4*)&g_Kb[b][n0 + nn][c4 * 8] =
                *(const float4*)(sm + nn * 144 + 64 + c4 * 16);
        }
    } else {
        // direct stage: Ov bf16 [64 oc][264] pitch 528B
        #pragma unroll
        for (int m = 0; m < 2; m++) {
            int row0 = wOC * 32 + m * 16 + r;
            #pragma unroll
            for (int j = 0; j < 8; j++) {
                int n_ = wN * 64 + j * 8 + tq * 2;
                *(uint32_t*)(sm + row0 * 528 + n_ * 2) =
                    pack_bf16(acc[m][j][1] + bm[m][0], acc[m][j][0] + bm[m][0]);
                *(uint32_t*)(sm + (row0 + 8) * 528 + n_ * 2) =
                    pack_bf16(acc[m][j][3] + bm[m][1], acc[m][j][2] + bm[m][1]);
            }
        }
        __syncthreads();
        #pragma unroll
        for (int l = 0; l < 8; l++) {
            int idx = t + l * 256;
            int row = idx >> 5, n16 = idx & 31;
            *(float4*)&g_Vb[b][oc0 - 64 + row][n0 + n16 * 8] =
                *(const float4*)(sm + row * 528 + n16 * 16);
        }
    }
}

// ============================================================================
// Kernel B: flash attention, all-bf16 mma.sync + ldmatrix, no max trick.
// Software-pipelined: at iter i, QK(i) and PV(i-1) are independent MMA bursts;
// exp/pack of tile i is off the tensor critical path (consumed at iter i+1).
// 4-stage K/V ring, one __syncthreads per iteration.
// CTA: 64 queries x 128 E-cols. 8 warps = 4 M-groups x 2 E-groups.
// ============================================================================
#define OFF_Q 0
#define OFF_S 5120
#define STAGE_B 23552          // K 5120 + V 18432
#define ATTN_SMEM_B 99328      // 5120 + 4*23552

__global__ __launch_bounds__(256, 2) void attn_kernel(
    const float* __restrict__ x,
    const float* __restrict__ gamma_p,
    float* __restrict__ out)
{
    extern __shared__ char smem[];
    const uint32_t sb = smem_u32(smem);
    const int t = threadIdx.x, wid = t >> 5, lane = t & 31;
    const int b = blockIdx.z;
    const int n0 = blockIdx.x * 64;
    const int e0 = blockIdx.y * 128;
    const int wM = wid & 3, wE = wid >> 2;
    const int r = lane >> 2, tq = lane & 3;

    const int krow = t >> 2, kch = t & 3;

    // ---- prologue: group0 = Q + tile0, group1 = tile1 ----
    cpa16(sb + OFF_Q + krow * 80 + kch * 16, &g_Qb[b][n0 + krow][kch * 8]);
    {
        uint32_t st = sb + OFF_S;
        cpa16(st + krow * 80 + kch * 16, &g_Kb[b][krow][kch * 8]);
        #pragma unroll
        for (int l = 0; l < 4; l++) {
            int c = t + l * 256;
            int e = c >> 3, ch8 = c & 7;
            cpa16(st + 5120 + e * 144 + ch8 * 16, &g_Vb[b][e0 + e][ch8 * 8]);
        }
    }
    CP_COMMIT();
    {
        uint32_t st = sb + OFF_S + STAGE_B;
        cpa16(st + krow * 80 + kch * 16, &g_Kb[b][64 + krow][kch * 8]);
        #pragma unroll
        for (int l = 0; l < 4; l++) {
            int c = t + l * 256;
            int e = c >> 3, ch8 = c & 7;
            cpa16(st + 5120 + e * 144 + ch8 * 16, &g_Vb[b][e0 + e][64 + ch8 * 8]);
        }
    }
    CP_COMMIT();
    CP_WAIT1();
    __syncthreads();

    // persistent Q fragments
    uint32_t qa[2][4];
    {
        uint32_t qaddr = sb + OFF_Q + (wM * 16 + (lane & 15)) * 80 + (lane >> 4) * 16;
        ldmx4(qa[0], qaddr);
        ldmx4(qa[1], qaddr + 32);
    }
    const uint32_t k_off = (lane & 7) * 80 + (lane >> 3) * 16;
    const uint32_t v_off = (wE * 64 + (lane & 7)) * 144 + (lane >> 3) * 16;

    float o[8][4];
    #pragma unroll
    for (int tn = 0; tn < 8; tn++)
        #pragma unroll
        for (int j = 0; j < 4; j++) o[tn][j] = 0.f;
    float sum0 = 0.f, sum1 = 0.f;
    uint32_t pa[4][4];                         // P frags of tile i-1

    for (int i = 0; i < 64; i++) {
        // tile i arrived? (own copies) then publish/protect barrier
        if (i < 63) { CP_WAIT1(); } else { CP_WAIT0(); }
        __syncthreads();
        // prefetch tile i+2 into stage (i+2)&3 (overwrites tile i-2, whose
        // reads ended at iter i-1, before this barrier)
        if (i + 2 < 64) {
            int m0 = (i + 2) * 64;
            uint32_t st = sb + OFF_S + ((i + 2) & 3) * STAGE_B;
            cpa16(st + krow * 80 + kch * 16, &g_Kb[b][m0 + krow][kch * 8]);
            #pragma unroll
            for (int l = 0; l < 4; l++) {
                int c = t + l * 256;
                int e = c >> 3, ch8 = c & 7;
                cpa16(st + 5120 + e * 144 + ch8 * 16, &g_Vb[b][e0 + e][m0 + ch8 * 8]);
            }
            CP_COMMIT();
        }

        const uint32_t kb = sb + OFF_S + (i & 3) * STAGE_B;

        // S = Q K^T for tile i
        float sc[8][4];
        #pragma unroll
        for (int tn = 0; tn < 8; tn++) {
            uint32_t kf[4];
            ldmx4(kf, kb + tn * 640 + k_off);
            sc[tn][0] = sc[tn][1] = sc[tn][2] = sc[tn][3] = 0.f;
            mma_bf16(sc[tn], qa[0], kf[0], kf[1]);
            mma_bf16(sc[tn], qa[1], kf[2], kf[3]);
        }

        // O += P(i-1) V(i-1)  — independent of the QK burst above
        if (i) {
            const uint32_t vbp = sb + OFF_S + ((i - 1) & 3) * STAGE_B + 5120;
            #pragma unroll
            for (int eb = 0; eb < 8; eb++) {
                uint32_t v0[4], v1[4];
                ldmx4(v0, vbp + v_off + eb * 1152);
                ldmx4(v1, vbp + v_off + eb * 1152 + 64);
                mma_bf16(o[eb], pa[0], v0[0], v0[1]);
                mma_bf16(o[eb], pa[1], v0[2], v0[3]);
                mma_bf16(o[eb], pa[2], v1[0], v1[1]);
                mma_bf16(o[eb], pa[3], v1[2], v1[3]);
            }
        }

        // P(i) = 2^S, rowsums, pack (consumed at iter i+1)
        #pragma unroll
        for (int tn = 0; tn < 8; tn++) {
            float p0 = fexp2(sc[tn][0]);
            float p1 = fexp2(sc[tn][1]);
            float p2 = fexp2(sc[tn][2]);
            float p3 = fexp2(sc[tn][3]);
            sum0 += p0 + p1;
            sum1 += p2 + p3;
            sc[tn][0] = p0; sc[tn][1] = p1; sc[tn][2] = p2; sc[tn][3] = p3;
        }
        #pragma unroll
        for (int s = 0; s < 4; s++) {
            pa[s][0] = pack_bf16(sc[2 * s][1],     sc[2 * s][0]);
            pa[s][1] = pack_bf16(sc[2 * s][3],     sc[2 * s][2]);
            pa[s][2] = pack_bf16(sc[2 * s + 1][1], sc[2 * s + 1][0]);
            pa[s][3] = pack_bf16(sc[2 * s + 1][3], sc[2 * s + 1][2]);
        }
    }

    // tail: O += P(63) V(63)
    {
        const uint32_t vbp = sb + OFF_S + (63 & 3) * STAGE_B + 5120;
        #pragma unroll
        for (int eb = 0; eb < 8; eb++) {
            uint32_t v0[4], v1[4];
            ldmx4(v0, vbp + v_off + eb * 1152);
            ldmx4(v1, vbp + v_off + eb * 1152 + 64);
            mma_bf16(o[eb], pa[0], v0[0], v0[1]);
            mma_bf16(o[eb], pa[1], v0[2], v0[3]);
            mma_bf16(o[eb], pa[2], v1[0], v1[1]);
            mma_bf16(o[eb], pa[3], v1[2], v1[3]);
        }
    }

    // ---- epilogue ----
    sum0 += __shfl_xor_sync(0xffffffffu, sum0, 1);
    sum0 += __shfl_xor_sync(0xffffffffu, sum0, 2);
    sum1 += __shfl_xor_sync(0xffffffffu, sum1, 1);
    sum1 += __shfl_xor_sync(0xffffffffu, sum1, 2);
    const float g = gamma_p[0];
    const float sc0 = g / sum0, sc1 = g / sum1;

    __syncthreads();
    float* os = (float*)smem;                 // [64][133]
    #pragma unroll
    for (int tn = 0; tn < 8; tn++) {
        int e = wE * 64 + tn * 8 + 2 * tq;
        os[(wM * 16 + r) * 133 + e]         = o[tn][0] * sc0;
        os[(wM * 16 + r) * 133 + e + 1]     = o[tn][1] * sc0;
        os[(wM * 16 + r + 8) * 133 + e]     = o[tn][2] * sc1;
        os[(wM * 16 + r + 8) * 133 + e + 1] = o[tn][3] * sc1;
    }
    __syncthreads();
    #pragma unroll 8
    for (int l = 0; l < 32; l++) {
        int idx = t + l * 256;
        int n = idx & 63, e = idx >> 6;
        int gi = (b * NC + e0 + e) * NHW + n0 + n;
        out[gi] = os[n * 133 + e] + x[gi];
    }
}

// ============================================================================
extern "C" void kernel_launch(void* const* d_in, const int* in_sizes, int n_in,
                              void* d_out, int out_size) {
    (void)in_sizes; (void)n_in; (void)out_size;
    const float* x     = (const float*)d_in[0];
    const float* Wq    = (const float*)d_in[1];
    const float* bq    = (const float*)d_in[2];
    const float* Wk    = (const float*)d_in[3];
    const float* bk    = (const float*)d_in[4];
    const float* Wv    = (const float*)d_in[5];
    const float* bv    = (const float*)d_in[6];
    const float* gamma = (const float*)d_in[7];
    float* out = (float*)d_out;

    cudaFuncSetAttribute(qkv_kernel,
                         cudaFuncAttributeMaxDynamicSharedMemorySize, QKV_SMEM2);
    cudaFuncSetAttribute(attn_kernel,
                         cudaFuncAttributeMaxDynamicSharedMemorySize, ATTN_SMEM_B);

    dim3 gA(16, 5, NB);
    qkv_kernel<<<gA, 256, QKV_SMEM2>>>(x, Wq, bq, Wk, bk, Wv, bv);

    dim3 gB(64, 2, NB);
    attn_kernel<<<gB, 256, ATTN_SMEM_B>>>(x, gamma, out);
}

// round 8
// speedup vs baseline: 1.1440x; 1.1440x over previous
#include <cuda_runtime.h>
#include <cuda_bf16.h>
#include <cstdint>

#define NB 8
#define NC 256
#define NHW 4096
#define ND 32

typedef unsigned long long ull;

// Static device scratch
__device__ __nv_bfloat16 g_Qb[NB][NHW][ND];    // q * log2(e), [b][n][d] bf16
__device__ __nv_bfloat16 g_Kb[NB][NHW][ND];    // [b][n][d] bf16
__device__ __nv_bfloat16 g_Vb[NB][NC][NHW];    // [b][e][n] bf16

// ---------------------------------------------------------------------------
// helpers
// ---------------------------------------------------------------------------
__device__ __forceinline__ uint32_t smem_u32(const void* p) {
    uint32_t a;
    asm("{ .reg .u64 t; cvta.to.shared.u64 t, %1; cvt.u32.u64 %0, t; }"
        : "=r"(a) : "l"(p));
    return a;
}
__device__ __forceinline__ float fexp2(float v) {
    float r; asm("ex2.approx.ftz.f32 %0, %1;" : "=f"(r) : "f"(v)); return r;
}
// d = {hi, lo} packed bf16x2
__device__ __forceinline__ uint32_t pack_bf16(float hi, float lo) {
    uint32_t r; asm("cvt.rn.bf16x2.f32 %0, %1, %2;" : "=r"(r) : "f"(hi), "f"(lo));
    return r;
}
__device__ __forceinline__ void mma_bf16(float c[4], const uint32_t a[4],
                                         uint32_t b0, uint32_t b1) {
    asm volatile(
        "mma.sync.aligned.m16n8k16.row.col.f32.bf16.bf16.f32 "
        "{%0,%1,%2,%3}, {%4,%5,%6,%7}, {%8,%9}, {%0,%1,%2,%3};"
        : "+f"(c[0]), "+f"(c[1]), "+f"(c[2]), "+f"(c[3])
        : "r"(a[0]), "r"(a[1]), "r"(a[2]), "r"(a[3]), "r"(b0), "r"(b1));
}
__device__ __forceinline__ void ldmx4(uint32_t r[4], uint32_t a) {
    asm volatile("ldmatrix.sync.aligned.m8n8.x4.shared.b16 {%0,%1,%2,%3}, [%4];"
        : "=r"(r[0]), "=r"(r[1]), "=r"(r[2]), "=r"(r[3]) : "r"(a));
}
__device__ __forceinline__ void ldmx4t(uint32_t r[4], uint32_t a) {
    asm volatile("ldmatrix.sync.aligned.m8n8.x4.trans.shared.b16 {%0,%1,%2,%3}, [%4];"
        : "=r"(r[0]), "=r"(r[1]), "=r"(r[2]), "=r"(r[3]) : "r"(a));
}
__device__ __forceinline__ void cpa16(uint32_t s, const void* g) {
    asm volatile("cp.async.cg.shared.global [%0], [%1], 16;"
                 :: "r"(s), "l"(__cvta_generic_to_global(g)) : "memory");
}
__device__ __forceinline__ void sts32(uint32_t a, uint32_t v) {
    asm volatile("st.shared.b32 [%0], %1;" :: "r"(a), "r"(v) : "memory");
}
#define CP_COMMIT() asm volatile("cp.async.commit_group;" ::: "memory")
#define CP_WAIT1()  asm volatile("cp.async.wait_group 1;" ::: "memory")
#define CP_WAIT0()  asm volatile("cp.async.wait_group 0;" ::: "memory")

// ============================================================================
// Kernel A: fused QKV projection, bf16 tensor cores (unchanged, ~15us).
// ============================================================================
#define QW_PITCH 528
#define OFF_W 0
#define OFF_BIAS 33792
#define OFF_X 34048
#define QKV_SMEM2 50944

__global__ __launch_bounds__(256) void qkv_kernel(
    const float* __restrict__ x,
    const float* __restrict__ Wq, const float* __restrict__ bq,
    const float* __restrict__ Wk, const float* __restrict__ bk,
    const float* __restrict__ Wv, const float* __restrict__ bv)
{
    extern __shared__ char sm[];
    const uint32_t sb = smem_u32(sm);
    const int b = blockIdx.z;
    const int oc0 = blockIdx.y * 64;
    const int n0 = blockIdx.x * 256;
    const int t = threadIdx.x, wid = t >> 5, lane = t & 31;
    const int wOC = wid & 1, wN = wid >> 1;
    const int r = lane >> 2, tq = lane & 3;

    #pragma unroll
    for (int l = 0; l < 16; l++) {
        int idx = t + l * 256;
        int row = idx >> 6, c4 = idx & 63;
        const float* src;
        if (oc0 == 0) src = (row < 32) ? &Wq[row * 256 + c4 * 4]
                                       : &Wk[(row - 32) * 256 + c4 * 4];
        else          src = &Wv[(oc0 - 64 + row) * 256 + c4 * 4];
        float4 w = *(const float4*)src;
        *(uint2*)(sm + OFF_W + row * QW_PITCH + c4 * 8) =
            make_uint2(pack_bf16(w.y, w.x), pack_bf16(w.w, w.z));
    }
    if (t < 64) {
        float bias;
        if (oc0 == 0) bias = (t < 32) ? bq[t] : bk[t - 32];
        else          bias = bv[oc0 - 64 + t];
        ((float*)(sm + OFF_BIAS))[t] = bias;
    }

    float acc[2][8][4];
    #pragma unroll
    for (int m = 0; m < 2; m++)
        #pragma unroll
        for (int j = 0; j < 8; j++)
            #pragma unroll
            for (int q = 0; q < 4; q++) acc[m][j][q] = 0.f;

    float4 xr[8];
    #pragma unroll
    for (int l = 0; l < 8; l++) {
        int idx = t + l * 256;
        int cc = idx >> 6, n4 = idx & 63;
        xr[l] = *(const float4*)&x[(b * NC + cc) * NHW + n0 + n4 * 4];
    }

    for (int ch = 0; ch < 8; ch++) {
        __syncthreads();
        #pragma unroll
        for (int l = 0; l < 8; l++) {
            int idx = t + l * 256;
            int cc = idx >> 6, n4 = idx & 63;
            *(uint2*)(sm + OFF_X + cc * QW_PITCH + n4 * 8) =
                make_uint2(pack_bf16(xr[l].y, xr[l].x), pack_bf16(xr[l].w, xr[l].z));
        }
        __syncthreads();
        if (ch + 1 < 8) {
            int c0n = (ch + 1) * 32;
            #pragma unroll
            for (int l = 0; l < 8; l++) {
                int idx = t + l * 256;
                int cc = idx >> 6, n4 = idx & 63;
                xr[l] = *(const float4*)&x[(b * NC + c0n + cc) * NHW + n0 + n4 * 4];
            }
        }
        #pragma unroll
        for (int ks = 0; ks < 2; ks++) {
            const int cb = ks * 16;
            uint32_t a0[4], a1[4];
            uint32_t wadr = sb + OFF_W + (wOC * 32 + (lane & 15)) * QW_PITCH
                            + (ch * 32 + cb) * 2 + (lane >> 4) * 16;
            ldmx4(a0, wadr);
            ldmx4(a1, wadr + 16 * QW_PITCH);
            uint32_t bt[4][4];
            #pragma unroll
            for (int nb = 0; nb < 4; nb++) {
                uint32_t xadr = sb + OFF_X
                    + (cb + (lane & 7) + ((lane >> 3) & 1) * 8) * QW_PITCH
                    + (wN * 64 + nb * 16 + (lane >> 4) * 8) * 2;
                ldmx4t(bt[nb], xadr);
            }
            #pragma unroll
            for (int nb = 0; nb < 4; nb++) {
                mma_bf16(acc[0][nb * 2],     a0, bt[nb][0], bt[nb][1]);
                mma_bf16(acc[0][nb * 2 + 1], a0, bt[nb][2], bt[nb][3]);
                mma_bf16(acc[1][nb * 2],     a1, bt[nb][0], bt[nb][1]);
                mma_bf16(acc[1][nb * 2 + 1], a1, bt[nb][2], bt[nb][3]);
            }
        }
    }
    __syncthreads();

    const float* bs = (const float*)(sm + OFF_BIAS);
    float bm[2][2];
    bm[0][0] = bs[wOC * 32 + r];      bm[0][1] = bs[wOC * 32 + r + 8];
    bm[1][0] = bs[wOC * 32 + 16 + r]; bm[1][1] = bs[wOC * 32 + 16 + r + 8];
    __syncthreads();

    if (oc0 == 0) {
        const float scl = (wOC == 0) ? 1.4426950408889634f : 1.0f;
        #pragma unroll
        for (int m = 0; m < 2; m++) {
            int oc_r0 = wOC * 32 + m * 16 + r;
            #pragma unroll
            for (int j = 0; j < 8; j++) {
                int n_ = wN * 64 + j * 8 + tq * 2;
                *(__nv_bfloat16*)(sm + n_ * 144 + oc_r0 * 2) =
                    __float2bfloat16((acc[m][j][0] + bm[m][0]) * scl);
                *(__nv_bfloat16*)(sm + (n_ + 1) * 144 + oc_r0 * 2) =
                    __float2bfloat16((acc[m][j][1] + bm[m][0]) * scl);
                *(__nv_bfloat16*)(sm + n_ * 144 + (oc_r0 + 8) * 2) =
                    __float2bfloat16((acc[m][j][2] + bm[m][1]) * scl);
                *(__nv_bfloat16*)(sm + (n_ + 1) * 144 + (oc_r0 + 8) * 2) =
                    __float2bfloat16((acc[m][j][3] + bm[m][1]) * scl);
            }
        }
        __syncthreads();
        #pragma unroll
        for (int l = 0; l < 4; l++) {
            int idx = t + l * 256;
            int nn = idx >> 2, c4 = idx & 3;
            *(float4*)&g_Qb[b][n0 + nn][c4 * 8] =
                *(const float4*)(sm + nn * 144 + c4 * 16);
            *(float4*)&g_Kb[b][n0 + nn][c4 * 8] =
                *(const float4*)(sm + nn * 144 + 64 + c4 * 16);
        }
    } else {
        #pragma unroll
        for (int m = 0; m < 2; m++) {
            int row0 = wOC * 32 + m * 16 + r;
            #pragma unroll
            for (int j = 0; j < 8; j++) {
                int n_ = wN * 64 + j * 8 + tq * 2;
                *(uint32_t*)(sm + row0 * 528 + n_ * 2) =
                    pack_bf16(acc[m][j][1] + bm[m][0], acc[m][j][0] + bm[m][0]);
                *(uint32_t*)(sm + (row0 + 8) * 528 + n_ * 2) =
                    pack_bf16(acc[m][j][3] + bm[m][1], acc[m][j][2] + bm[m][1]);
            }
        }
        __syncthreads();
        #pragma unroll
        for (int l = 0; l < 8; l++) {
            int idx = t + l * 256;
            int row = idx >> 5, n16 = idx & 31;
            *(float4*)&g_Vb[b][oc0 - 64 + row][n0 + n16 * 8] =
                *(const float4*)(sm + row * 528 + n16 * 16);
        }
    }
}

// ============================================================================
// Kernel B: warp-specialized flash attention.
// CTA = 64 q x 256 E, 512 threads = 16 warps = 4 Mg x 4 Eg. 1 CTA/SM.
// Per M-group, the wE==0 warp is the S-producer: QK + exp(f32) + STS P(bf16).
// All warps ldmatrix P and run PV(i-1). QK/exp computed ONCE per CTA (dedup).
// 4-stage K/V ring (prefetch distance 2), 2-buffer P, 1 barrier/iter.
// ============================================================================
#define A_OFF_Q 0                 // 64 x 80B
#define A_OFF_K 5120              // 4 stages x 5120
#define A_OFF_V 25600             // 4 stages x 36864 (256e x 144B)
#define A_OFF_P 173056            // 2 bufs x 9216 (64 x 144B)
#define A_OFF_SUM 191488          // 64 f32
#define ATTN_SMEM_C 191744

__global__ __launch_bounds__(512, 1) void attn_kernel(
    const float* __restrict__ x,
    const float* __restrict__ gamma_p,
    float* __restrict__ out)
{
    extern __shared__ char smem[];
    const uint32_t sb = smem_u32(smem);
    const int t = threadIdx.x, wid = t >> 5, lane = t & 31;
    const int b = blockIdx.y;
    const int n0 = blockIdx.x * 64;
    const int wM = wid & 3, wE = wid >> 2;
    const int r = lane >> 2, tq = lane & 3;

    // ---- prologue: group0 = {Q, K0, V0}, group1 = {K1, V1} ----
    if (t < 256) {
        int row = t >> 2, ch = t & 3;
        cpa16(sb + A_OFF_Q + row * 80 + ch * 16, &g_Qb[b][n0 + row][ch * 8]);
        cpa16(sb + A_OFF_K + row * 80 + ch * 16, &g_Kb[b][row][ch * 8]);
    }
    #pragma unroll
    for (int l = 0; l < 4; l++) {
        int idx = t + l * 512;
        int e = idx >> 3, ch = idx & 7;
        cpa16(sb + A_OFF_V + e * 144 + ch * 16, &g_Vb[b][e][ch * 8]);
    }
    CP_COMMIT();
    if (t < 256) {
        int row = t >> 2, ch = t & 3;
        cpa16(sb + A_OFF_K + 5120 + row * 80 + ch * 16, &g_Kb[b][64 + row][ch * 8]);
    }
    #pragma unroll
    for (int l = 0; l < 4; l++) {
        int idx = t + l * 512;
        int e = idx >> 3, ch = idx & 7;
        cpa16(sb + A_OFF_V + 36864 + e * 144 + ch * 16, &g_Vb[b][e][64 + ch * 8]);
    }
    CP_COMMIT();

    const uint32_t k_off = (lane & 7) * 80 + (lane >> 3) * 16;
    const uint32_t v_off = (wE * 64 + (lane & 7)) * 144 + (lane >> 3) * 16;
    const uint32_t p_ld_off = (wM * 16 + (lane & 15)) * 144 + (lane >> 4) * 16;

    uint32_t qa[2][4];
    float o[8][4];
    #pragma unroll
    for (int eb = 0; eb < 8; eb++)
        #pragma unroll
        for (int j = 0; j < 4; j++) o[eb][j] = 0.f;
    float sum0 = 0.f, sum1 = 0.f;

    for (int i = 0; i < 64; i++) {
        if (i < 62) { CP_WAIT1(); } else { CP_WAIT0(); }
        __syncthreads();                       // tile i ready, P(i-1) visible

        if (i + 2 < 64) {                      // prefetch tile i+2
            int m0 = (i + 2) * 64;
            uint32_t kst = sb + A_OFF_K + ((i + 2) & 3) * 5120;
            if (t < 256) {
                int row = t >> 2, ch = t & 3;
                cpa16(kst + row * 80 + ch * 16, &g_Kb[b][m0 + row][ch * 8]);
            }
            uint32_t vst = sb + A_OFF_V + ((i + 2) & 3) * 36864;
            #pragma unroll
            for (int l = 0; l < 4; l++) {
                int idx = t + l * 512;
                int e = idx >> 3, ch = idx & 7;
                cpa16(vst + e * 144 + ch * 16, &g_Vb[b][e][m0 + ch * 8]);
            }
            CP_COMMIT();
        }

        if (wE == 0) {
            // -------- producer: S = QK^T, exp, STS P --------
            if (i == 0) {
                uint32_t qaddr = sb + A_OFF_Q + (wM * 16 + (lane & 15)) * 80
                                 + (lane >> 4) * 16;
                ldmx4(qa[0], qaddr);
                ldmx4(qa[1], qaddr + 32);
            }
            const uint32_t kb = sb + A_OFF_K + (i & 3) * 5120;
            const uint32_t pbuf = sb + A_OFF_P + (i & 1) * 9216;
            float sc[8][4];
            #pragma unroll
            for (int tn = 0; tn < 8; tn++) {
                uint32_t kf[4];
                ldmx4(kf, kb + tn * 640 + k_off);
                sc[tn][0] = sc[tn][1] = sc[tn][2] = sc[tn][3] = 0.f;
                mma_bf16(sc[tn], qa[0], kf[0], kf[1]);
                mma_bf16(sc[tn], qa[1], kf[2], kf[3]);
            }
            #pragma unroll
            for (int tn = 0; tn < 8; tn++) {
                float p0 = fexp2(sc[tn][0]);
                float p1 = fexp2(sc[tn][1]);
                float p2 = fexp2(sc[tn][2]);
                float p3 = fexp2(sc[tn][3]);
                sum0 += p0 + p1;
                sum1 += p2 + p3;
                sts32(pbuf + (wM * 16 + r) * 144 + (8 * tn + 2 * tq) * 2,
                      pack_bf16(p1, p0));
                sts32(pbuf + (wM * 16 + r + 8) * 144 + (8 * tn + 2 * tq) * 2,
                      pack_bf16(p3, p2));
            }
        }

        if (i > 0) {
            // -------- all warps: O += P(i-1) V(i-1) --------
            const uint32_t pb = sb + A_OFF_P + ((i - 1) & 1) * 9216;
            const uint32_t vb = sb + A_OFF_V + ((i - 1) & 3) * 36864;
            uint32_t pf[4][4];
            ldmx4(pf[0], pb + p_ld_off);
            ldmx4(pf[1], pb + p_ld_off + 32);
            ldmx4(pf[2], pb + p_ld_off + 64);
            ldmx4(pf[3], pb + p_ld_off + 96);
            #pragma unroll
            for (int eb = 0; eb < 8; eb++) {
                uint32_t v0[4], v1[4];
                ldmx4(v0, vb + v_off + eb * 1152);
                ldmx4(v1, vb + v_off + eb * 1152 + 64);
                mma_bf16(o[eb], pf[0], v0[0], v0[1]);
                mma_bf16(o[eb], pf[1], v0[2], v0[3]);
                mma_bf16(o[eb], pf[2], v1[0], v1[1]);
                mma_bf16(o[eb], pf[3], v1[2], v1[3]);
            }
        }
    }

    // ---- tail: O += P(63) V(63) ----
    __syncthreads();
    {
        const uint32_t pb = sb + A_OFF_P + (63 & 1) * 9216;
        const uint32_t vb = sb + A_OFF_V + (63 & 3) * 36864;
        uint32_t pf[4][4];
        ldmx4(pf[0], pb + p_ld_off);
        ldmx4(pf[1], pb + p_ld_off + 32);
        ldmx4(pf[2], pb + p_ld_off + 64);
        ldmx4(pf[3], pb + p_ld_off + 96);
        #pragma unroll
        for (int eb = 0; eb < 8; eb++) {
            uint32_t v0[4], v1[4];
            ldmx4(v0, vb + v_off + eb * 1152);
            ldmx4(v1, vb + v_off + eb * 1152 + 64);
            mma_bf16(o[eb], pf[0], v0[0], v0[1]);
            mma_bf16(o[eb], pf[1], v0[2], v0[3]);
            mma_bf16(o[eb], pf[2], v1[0], v1[1]);
            mma_bf16(o[eb], pf[3], v1[2], v1[3]);
        }
    }

    // ---- share rowsums ----
    float* sums = (float*)(smem + A_OFF_SUM);
    if (wE == 0) {
        sum0 += __shfl_xor_sync(0xffffffffu, sum0, 1);
        sum0 += __shfl_xor_sync(0xffffffffu, sum0, 2);
        sum1 += __shfl_xor_sync(0xffffffffu, sum1, 1);
        sum1 += __shfl_xor_sync(0xffffffffu, sum1, 2);
        if (tq == 0) {
            sums[wM * 16 + r] = sum0;
            sums[wM * 16 + r + 8] = sum1;
        }
    }
    __syncthreads();                           // sums visible; V/K stages free
    const float g = gamma_p[0];
    const float s0 = g / sums[wM * 16 + r];
    const float s1 = g / sums[wM * 16 + r + 8];

    // ---- stage O (transpose) + residual write ----
    float* os = (float*)smem;                  // [64][265] f32
    #pragma unroll
    for (int eb = 0; eb < 8; eb++) {
        int e = wE * 64 + eb * 8 + 2 * tq;
        os[(wM * 16 + r) * 265 + e]         = o[eb][0] * s0;
        os[(wM * 16 + r) * 265 + e + 1]     = o[eb][1] * s0;
        os[(wM * 16 + r + 8) * 265 + e]     = o[eb][2] * s1;
        os[(wM * 16 + r + 8) * 265 + e + 1] = o[eb][3] * s1;
    }
    __syncthreads();
    #pragma unroll 8
    for (int l = 0; l < 32; l++) {
        int idx = t + l * 512;
        int n = idx & 63, e = idx >> 6;
        int gi = (b * NC + e) * NHW + n0 + n;
        out[gi] = os[n * 265 + e] + x[gi];
    }
}

// ============================================================================
extern "C" void kernel_launch(void* const* d_in, const int* in_sizes, int n_in,
                              void* d_out, int out_size) {
    (void)in_sizes; (void)n_in; (void)out_size;
    const float* x     = (const float*)d_in[0];
    const float* Wq    = (const float*)d_in[1];
    const float* bq    = (const float*)d_in[2];
    const float* Wk    = (const float*)d_in[3];
    const float* bk    = (const float*)d_in[4];
    const float* Wv    = (const float*)d_in[5];
    const float* bv    = (const float*)d_in[6];
    const float* gamma = (const float*)d_in[7];
    float* out = (float*)d_out;

    cudaFuncSetAttribute(qkv_kernel,
                         cudaFuncAttributeMaxDynamicSharedMemorySize, QKV_SMEM2);
    cudaFuncSetAttribute(attn_kernel,
                         cudaFuncAttributeMaxDynamicSharedMemorySize, ATTN_SMEM_C);

    dim3 gA(16, 5, NB);
    qkv_kernel<<<gA, 256, QKV_SMEM2>>>(x, Wq, bq, Wk, bk, Wv, bv);

    dim3 gB(64, NB);
    attn_kernel<<<gB, 512, ATTN_SMEM_C>>>(x, gamma, out);
}

// round 10
// speedup vs baseline: 1.1848x; 1.0357x over previous
#include <cuda_runtime.h>
#include <cuda_bf16.h>
#include <cstdint>

#define NB 8
#define NC 256
#define NHW 4096
#define ND 32

typedef unsigned long long ull;

// Static device scratch
__device__ __nv_bfloat16 g_Qb[NB][NHW][ND];    // q * log2(e), [b][n][d] bf16
__device__ __nv_bfloat16 g_Kb[NB][NHW][ND];    // [b][n][d] bf16
__device__ __nv_bfloat16 g_Vb[NB][NC][NHW];    // [b][e][n] bf16

// ---------------------------------------------------------------------------
// helpers
// ---------------------------------------------------------------------------
__device__ __forceinline__ uint32_t smem_u32(const void* p) {
    uint32_t a;
    asm("{ .reg .u64 t; cvta.to.shared.u64 t, %1; cvt.u32.u64 %0, t; }"
        : "=r"(a) : "l"(p));
    return a;
}
__device__ __forceinline__ float fexp2(float v) {
    float r; asm("ex2.approx.ftz.f32 %0, %1;" : "=f"(r) : "f"(v)); return r;
}
// d = {hi, lo} packed bf16x2
__device__ __forceinline__ uint32_t pack_bf16(float hi, float lo) {
    uint32_t r; asm("cvt.rn.bf16x2.f32 %0, %1, %2;" : "=r"(r) : "f"(hi), "f"(lo));
    return r;
}
__device__ __forceinline__ void mma_bf16(float c[4], const uint32_t a[4],
                                         uint32_t b0, uint32_t b1) {
    asm volatile(
        "mma.sync.aligned.m16n8k16.row.col.f32.bf16.bf16.f32 "
        "{%0,%1,%2,%3}, {%4,%5,%6,%7}, {%8,%9}, {%0,%1,%2,%3};"
        : "+f"(c[0]), "+f"(c[1]), "+f"(c[2]), "+f"(c[3])
        : "r"(a[0]), "r"(a[1]), "r"(a[2]), "r"(a[3]), "r"(b0), "r"(b1));
}
__device__ __forceinline__ void ldmx4(uint32_t r[4], uint32_t a) {
    asm volatile("ldmatrix.sync.aligned.m8n8.x4.shared.b16 {%0,%1,%2,%3}, [%4];"
        : "=r"(r[0]), "=r"(r[1]), "=r"(r[2]), "=r"(r[3]) : "r"(a));
}
__device__ __forceinline__ void ldmx4t(uint32_t r[4], uint32_t a) {
    asm volatile("ldmatrix.sync.aligned.m8n8.x4.trans.shared.b16 {%0,%1,%2,%3}, [%4];"
        : "=r"(r[0]), "=r"(r[1]), "=r"(r[2]), "=r"(r[3]) : "r"(a));
}
__device__ __forceinline__ void cpa16(uint32_t s, const void* g) {
    asm volatile("cp.async.cg.shared.global [%0], [%1], 16;"
                 :: "r"(s), "l"(__cvta_generic_to_global(g)) : "memory");
}
#define CP_COMMIT() asm volatile("cp.async.commit_group;" ::: "memory")
#define CP_WAIT1()  asm volatile("cp.async.wait_group 1;" ::: "memory")
#define CP_WAIT0()  asm volatile("cp.async.wait_group 0;" ::: "memory")

// ============================================================================
// Kernel A: fused QKV projection, bf16 tensor cores (unchanged, ~15us).
// ============================================================================
#define QW_PITCH 528
#define OFF_W 0
#define OFF_BIAS 33792
#define OFF_X 34048
#define QKV_SMEM2 50944

__global__ __launch_bounds__(256) void qkv_kernel(
    const float* __restrict__ x,
    const float* __restrict__ Wq, const float* __restrict__ bq,
    const float* __restrict__ Wk, const float* __restrict__ bk,
    const float* __restrict__ Wv, const float* __restrict__ bv)
{
    extern __shared__ char sm[];
    const uint32_t sb = smem_u32(sm);
    const int b = blockIdx.z;
    const int oc0 = blockIdx.y * 64;
    const int n0 = blockIdx.x * 256;
    const int t = threadIdx.x, wid = t >> 5, lane = t & 31;
    const int wOC = wid & 1, wN = wid >> 1;
    const int r = lane >> 2, tq = lane & 3;

    #pragma unroll
    for (int l = 0; l < 16; l++) {
        int idx = t + l * 256;
        int row = idx >> 6, c4 = idx & 63;
        const float* src;
        if (oc0 == 0) src = (row < 32) ? &Wq[row * 256 + c4 * 4]
                                       : &Wk[(row - 32) * 256 + c4 * 4];
        else          src = &Wv[(oc0 - 64 + row) * 256 + c4 * 4];
        float4 w = *(const float4*)src;
        *(uint2*)(sm + OFF_W + row * QW_PITCH + c4 * 8) =
            make_uint2(pack_bf16(w.y, w.x), pack_bf16(w.w, w.z));
    }
    if (t < 64) {
        float bias;
        if (oc0 == 0) bias = (t < 32) ? bq[t] : bk[t - 32];
        else          bias = bv[oc0 - 64 + t];
        ((float*)(sm + OFF_BIAS))[t] = bias;
    }

    float acc[2][8][4];
    #pragma unroll
    for (int m = 0; m < 2; m++)
        #pragma unroll
        for (int j = 0; j < 8; j++)
            #pragma unroll
            for (int q = 0; q < 4; q++) acc[m][j][q] = 0.f;

    float4 xr[8];
    #pragma unroll
    for (int l = 0; l < 8; l++) {
        int idx = t + l * 256;
        int cc = idx >> 6, n4 = idx & 63;
        xr[l] = *(const float4*)&x[(b * NC + cc) * NHW + n0 + n4 * 4];
    }

    for (int ch = 0; ch < 8; ch++) {
        __syncthreads();
        #pragma unroll
        for (int l = 0; l < 8; l++) {
            int idx = t + l * 256;
            int cc = idx >> 6, n4 = idx & 63;
            *(uint2*)(sm + OFF_X + cc * QW_PITCH + n4 * 8) =
                make_uint2(pack_bf16(xr[l].y, xr[l].x), pack_bf16(xr[l].w, xr[l].z));
        }
        __syncthreads();
        if (ch + 1 < 8) {
            int c0n = (ch + 1) * 32;
            #pragma unroll
            for (int l = 0; l < 8; l++) {
                int idx = t + l * 256;
                int cc = idx >> 6, n4 = idx & 63;
                xr[l] = *(const float4*)&x[(b * NC + c0n + cc) * NHW + n0 + n4 * 4];
            }
        }
        #pragma unroll
        for (int ks = 0; ks < 2; ks++) {
            const int cb = ks * 16;
            uint32_t a0[4], a1[4];
            uint32_t wadr = sb + OFF_W + (wOC * 32 + (lane & 15)) * QW_PITCH
                            + (ch * 32 + cb) * 2 + (lane >> 4) * 16;
            ldmx4(a0, wadr);
            ldmx4(a1, wadr + 16 * QW_PITCH);
            uint32_t bt[4][4];
            #pragma unroll
            for (int nb = 0; nb < 4; nb++) {
                uint32_t xadr = sb + OFF_X
                    + (cb + (lane & 7) + ((lane >> 3) & 1) * 8) * QW_PITCH
                    + (wN * 64 + nb * 16 + (lane >> 4) * 8) * 2;
                ldmx4t(bt[nb], xadr);
            }
            #pragma unroll
            for (int nb = 0; nb < 4; nb++) {
                mma_bf16(acc[0][nb * 2],     a0, bt[nb][0], bt[nb][1]);
                mma_bf16(acc[0][nb * 2 + 1], a0, bt[nb][2], bt[nb][3]);
                mma_bf16(acc[1][nb * 2],     a1, bt[nb][0], bt[nb][1]);
                mma_bf16(acc[1][nb * 2 + 1], a1, bt[nb][2], bt[nb][3]);
            }
        }
    }
    __syncthreads();

    const float* bs = (const float*)(sm + OFF_BIAS);
    float bm[2][2];
    bm[0][0] = bs[wOC * 32 + r];      bm[0][1] = bs[wOC * 32 + r + 8];
    bm[1][0] = bs[wOC * 32 + 16 + r]; bm[1][1] = bs[wOC * 32 + 16 + r + 8];
    __syncthreads();

    if (oc0 == 0) {
        const float scl = (wOC == 0) ? 1.4426950408889634f : 1.0f;
        #pragma unroll
        for (int m = 0; m < 2; m++) {
            int oc_r0 = wOC * 32 + m * 16 + r;
            #pragma unroll
            for (int j = 0; j < 8; j++) {
                int n_ = wN * 64 + j * 8 + tq * 2;
                *(__nv_bfloat16*)(sm + n_ * 144 + oc_r0 * 2) =
                    __float2bfloat16((acc[m][j][0] + bm[m][0]) * scl);
                *(__nv_bfloat16*)(sm + (n_ + 1) * 144 + oc_r0 * 2) =
                    __float2bfloat16((acc[m][j][1] + bm[m][0]) * scl);
                *(__nv_bfloat16*)(sm + n_ * 144 + (oc_r0 + 8) * 2) =
                    __float2bfloat16((acc[m][j][2] + bm[m][1]) * scl);
                *(__nv_bfloat16*)(sm + (n_ + 1) * 144 + (oc_r0 + 8) * 2) =
                    __float2bfloat16((acc[m][j][3] + bm[m][1]) * scl);
            }
        }
        __syncthreads();
        #pragma unroll
        for (int l = 0; l < 4; l++) {
            int idx = t + l * 256;
            int nn = idx >> 2, c4 = idx & 3;
            *(float4*)&g_Qb[b][n0 + nn][c4 * 8] =
                *(const float4*)(sm + nn * 144 + c4 * 16);
            *(float4*)&g_Kb[b][n0 + nn][c4 * 8] =
                *(const float4*)(sm + nn * 144 + 64 + c4 * 16);
        }
    } else {
        #pragma unroll
        for (int m = 0; m < 2; m++) {
            int row0 = wOC * 32 + m * 16 + r;
            #pragma unroll
            for (int j = 0; j < 8; j++) {
                int n_ = wN * 64 + j * 8 + tq * 2;
                *(uint32_t*)(sm + row0 * 528 + n_ * 2) =
                    pack_bf16(acc[m][j][1] + bm[m][0], acc[m][j][0] + bm[m][0]);
                *(uint32_t*)(sm + (row0 + 8) * 528 + n_ * 2) =
                    pack_bf16(acc[m][j][3] + bm[m][1], acc[m][j][2] + bm[m][1]);
            }
        }
        __syncthreads();
        #pragma unroll
        for (int l = 0; l < 8; l++) {
            int idx = t + l * 256;
            int row = idx >> 5, n16 = idx & 31;
            *(float4*)&g_Vb[b][oc0 - 64 + row][n0 + n16 * 8] =
                *(const float4*)(sm + row * 528 + n16 * 16);
        }
    }
}

// ============================================================================
// Kernel B: flash attention (round-5 structure, 3 CTAs/SM).
// Serial QK->exp->PV per warp, 3-stage K/V ring, 1 barrier/iter.
// exp/pack fused per tn-PAIR so only 8 logits are live at once -> fits the
// 84-reg budget of __launch_bounds__(256,3) (24 warps/SM vs 16).
// CTA: 64 queries x 128 E-cols. 8 warps = 4 M-groups x 2 E-groups.
// ============================================================================
#define OFF_Q 0
#define OFF_S 5120
#define STAGE_B 23552          // K 5120 + V 18432
#define ATTN_SMEM_B 75776      // 5120 + 3*23552; x3 CTAs = 227 KB + reserve

__global__ __launch_bounds__(256, 3) void attn_kernel(
    const float* __restrict__ x,
    const float* __restrict__ gamma_p,
    float* __restrict__ out)
{
    extern __shared__ char smem[];
    const uint32_t sb = smem_u32(smem);
    const int t = threadIdx.x, wid = t >> 5, lane = t & 31;
    const int b = blockIdx.z;
    const int n0 = blockIdx.x * 64;
    const int e0 = blockIdx.y * 128;
    const int wM = wid & 3, wE = wid >> 2;
    const int r = lane >> 2, tq = lane & 3;

    const int krow = t >> 2, kch = t & 3;

    // ---- prologue: group0 = Q + tile0, group1 = tile1 ----
    cpa16(sb + OFF_Q + krow * 80 + kch * 16, &g_Qb[b][n0 + krow][kch * 8]);
    {
        uint32_t st = sb + OFF_S;
        cpa16(st + krow * 80 + kch * 16, &g_Kb[b][krow][kch * 8]);
        #pragma unroll
        for (int l = 0; l < 4; l++) {
            int c = t + l * 256;
            int e = c >> 3, ch8 = c & 7;
            cpa16(st + 5120 + e * 144 + ch8 * 16, &g_Vb[b][e0 + e][ch8 * 8]);
        }
    }
    CP_COMMIT();
    {
        uint32_t st = sb + OFF_S + STAGE_B;
        cpa16(st + krow * 80 + kch * 16, &g_Kb[b][64 + krow][kch * 8]);
        #pragma unroll
        for (int l = 0; l < 4; l++) {
            int c = t + l * 256;
            int e = c >> 3, ch8 = c & 7;
            cpa16(st + 5120 + e * 144 + ch8 * 16, &g_Vb[b][e0 + e][64 + ch8 * 8]);
        }
    }
    CP_COMMIT();
    CP_WAIT1();
    __syncthreads();

    // persistent Q fragments
    uint32_t qa[2][4];
    {
        uint32_t qaddr = sb + OFF_Q + (wM * 16 + (lane & 15)) * 80 + (lane >> 4) * 16;
        ldmx4(qa[0], qaddr);
        ldmx4(qa[1], qaddr + 32);
    }
    const uint32_t k_off = (lane & 7) * 80 + (lane >> 3) * 16;
    const uint32_t v_off = (wE * 64 + (lane & 7)) * 144 + (lane >> 3) * 16;

    float o[8][4];
    #pragma unroll
    for (int tn = 0; tn < 8; tn++)
        #pragma unroll
        for (int j = 0; j < 4; j++) o[tn][j] = 0.f;
    float sum0 = 0.f, sum1 = 0.f;

    int s_cur = 0, s_pf = 2;                  // stage of tile i, stage of tile i+2
    for (int i = 0; i < 64; i++) {
        if (i) {
            if (i >= 63) { CP_WAIT0(); } else { CP_WAIT1(); }
            __syncthreads();
        }
        if (i + 2 < 64) {                      // prefetch tile i+2 (before compute)
            int m0 = (i + 2) * 64;
            uint32_t st = sb + OFF_S + s_pf * STAGE_B;
            cpa16(st + krow * 80 + kch * 16, &g_Kb[b][m0 + krow][kch * 8]);
            #pragma unroll
            for (int l = 0; l < 4; l++) {
                int c = t + l * 256;
                int e = c >> 3, ch8 = c & 7;
                cpa16(st + 5120 + e * 144 + ch8 * 16, &g_Vb[b][e0 + e][m0 + ch8 * 8]);
            }
            CP_COMMIT();
        }

        const uint32_t kb = sb + OFF_S + s_cur * STAGE_B;
        const uint32_t vb = kb + 5120;

        // S = Q K^T, exp, pack — fused per tn-pair (8 live logits max)
        uint32_t pa[4][4];
        #pragma unroll
        for (int s4 = 0; s4 < 4; s4++) {
            uint32_t kf[4];
            float sa[4], sbv[4];
            ldmx4(kf, kb + (2 * s4) * 640 + k_off);
            sa[0] = sa[1] = sa[2] = sa[3] = 0.f;
            mma_bf16(sa, qa[0], kf[0], kf[1]);
            mma_bf16(sa, qa[1], kf[2], kf[3]);
            ldmx4(kf, kb + (2 * s4 + 1) * 640 + k_off);
            sbv[0] = sbv[1] = sbv[2] = sbv[3] = 0.f;
            mma_bf16(sbv, qa[0], kf[0], kf[1]);
            mma_bf16(sbv, qa[1], kf[2], kf[3]);

            float p0 = fexp2(sa[0]),  p1 = fexp2(sa[1]);
            float p2 = fexp2(sa[2]),  p3 = fexp2(sa[3]);
            float q0 = fexp2(sbv[0]), q1 = fexp2(sbv[1]);
            float q2 = fexp2(sbv[2]), q3 = fexp2(sbv[3]);
            sum0 += p0 + p1 + q0 + q1;
            sum1 += p2 + p3 + q2 + q3;
            pa[s4][0] = pack_bf16(p1, p0);
            pa[s4][1] = pack_bf16(p3, p2);
            pa[s4][2] = pack_bf16(q1, q0);
            pa[s4][3] = pack_bf16(q3, q2);
        }

        // O += P V
        #pragma unroll
        for (int eb = 0; eb < 8; eb++) {
            uint32_t v0[4], v1[4];
            ldmx4(v0, vb + v_off + eb * 1152);
            ldmx4(v1, vb + v_off + eb * 1152 + 64);
            mma_bf16(o[eb], pa[0], v0[0], v0[1]);
            mma_bf16(o[eb], pa[1], v0[2], v0[3]);
            mma_bf16(o[eb], pa[2], v1[0], v1[1]);
            mma_bf16(o[eb], pa[3], v1[2], v1[3]);
        }

        s_cur = (s_cur == 2) ? 0 : s_cur + 1;
        s_pf  = (s_pf == 2)  ? 0 : s_pf + 1;
    }

    // ---- epilogue ----
    sum0 += __shfl_xor_sync(0xffffffffu, sum0, 1);
    sum0 += __shfl_xor_sync(0xffffffffu, sum0, 2);
    sum1 += __shfl_xor_sync(0xffffffffu, sum1, 1);
    sum1 += __shfl_xor_sync(0xffffffffu, sum1, 2);
    const float g = gamma_p[0];
    const float sc0 = g / sum0, sc1 = g / sum1;

    __syncthreads();
    float* os = (float*)smem;                 // [64][133]
    #pragma unroll
    for (int tn = 0; tn < 8; tn++) {
        int e = wE * 64 + tn * 8 + 2 * tq;
        os[(wM * 16 + r) * 133 + e]         = o[tn][0] * sc0;
        os[(wM * 16 + r) * 133 + e + 1]     = o[tn][1] * sc0;
        os[(wM * 16 + r + 8) * 133 + e]     = o[tn][2] * sc1;
        os[(wM * 16 + r + 8) * 133 + e + 1] = o[tn][3] * sc1;
    }
    __syncthreads();
    #pragma unroll 8
    for (int l = 0; l < 32; l++) {
        int idx = t + l * 256;
        int n = idx & 63, e = idx >> 6;
        int gi = (b * NC + e0 + e) * NHW + n0 + n;
        out[gi] = os[n * 133 + e] + x[gi];
    }
}

// ============================================================================
extern "C" void kernel_launch(void* const* d_in, const int* in_sizes, int n_in,
                              void* d_out, int out_size) {
    (void)in_sizes; (void)n_in; (void)out_size;
    const float* x     = (const float*)d_in[0];
    const float* Wq    = (const float*)d_in[1];
    const float* bq    = (const float*)d_in[2];
    const float* Wk    = (const float*)d_in[3];
    const float* bk    = (const float*)d_in[4];
    const float* Wv    = (const float*)d_in[5];
    const float* bv    = (const float*)d_in[6];
    const float* gamma = (const float*)d_in[7];
    float* out = (float*)d_out;

    cudaFuncSetAttribute(qkv_kernel,
                         cudaFuncAttributeMaxDynamicSharedMemorySize, QKV_SMEM2);
    cudaFuncSetAttribute(attn_kernel,
                         cudaFuncAttributeMaxDynamicSharedMemorySize, ATTN_SMEM_B);

    dim3 gA(16, 5, NB);
    qkv_kernel<<<gA, 256, QKV_SMEM2>>>(x, Wq, bq, Wk, bk, Wv, bv);

    dim3 gB(64, 2, NB);
    attn_kernel<<<gB, 256, ATTN_SMEM_B>>>(x, gamma, out);
}